// round 10
// baseline (speedup 1.0000x reference)
#include <cuda_runtime.h>
#include <cuda_bf16.h>

// ---------------------------------------------------------------------------
// GCN 3-layer. Per layer: support = H @ W ; agg[n] = sum_{e:dst=n} support[src_e]*val_e + b
// GEMM layers 1-2: tf32 mma.sync (m16n8k8) tensor-core GEMM, W pre-converted
//   to tf32 in smem (XOR-swizzled), ReLU fused into A staging.
// GEMM layer 3 (NO=16): FFMA register-tiled (small, keeps full fp32 precision).
// SpMM: gather-based with dst-bucketed packed (src,val) slots padded to x4.
// ---------------------------------------------------------------------------

#define MAX_NODES 100000
#define SLOTS 64   // max in-degree capacity; deg ~ Poisson(10), P(>=64) ~ 1e-30

static __device__ float g_sup[(size_t)MAX_NODES * 64];
static __device__ float g_hA[(size_t)MAX_NODES * 64];
static __device__ float g_hB[(size_t)MAX_NODES * 64];

static __device__ int  g_cnt[MAX_NODES];
static __device__ int2 g_bpair[(size_t)MAX_NODES * SLOTS];   // (src, val bits)

// ---------------------------------------------------------------------------
// Bucket build: zero counters, slot edges by dst, then pad to multiple of 4.
// ---------------------------------------------------------------------------
__global__ void zero_cnt_kernel(int n) {
    int i = blockIdx.x * blockDim.x + threadIdx.x;
    if (i < n) g_cnt[i] = 0;
}

__global__ void bucket_build_kernel(const int* __restrict__ src,
                                    const int* __restrict__ dst,
                                    const float* __restrict__ val, int E) {
    int e = blockIdx.x * blockDim.x + threadIdx.x;
    if (e >= E) return;
    int d = __ldg(dst + e);
    int slot = atomicAdd(&g_cnt[d], 1);
    if (slot < SLOTS)
        g_bpair[(size_t)d * SLOTS + slot] =
            make_int2(__ldg(src + e), __float_as_int(__ldg(val + e)));
}

__global__ void bucket_pad_kernel(int n) {
    int i = blockIdx.x * blockDim.x + threadIdx.x;
    if (i >= n) return;
    int c = min(g_cnt[i], SLOTS);
    int cp = min((c + 3) & ~3, SLOTS);
    int2* bp = g_bpair + (size_t)i * SLOTS;
    for (int s = c; s < cp; s++) bp[s] = make_int2(0, 0);
    g_cnt[i] = cp;
}

// ---------------------------------------------------------------------------
// Gather SpMM + bias:  out[n, :] = bias + sum_s sup[src_s, :] * val_s
// Group of G = D/2 threads per node; cnt padded to x4 -> no tail, MLP=4.
// ---------------------------------------------------------------------------
template <int D>
__global__ void __launch_bounds__(256) gather_spmm_kernel(
    const float* __restrict__ sup, const float* __restrict__ bias,
    float* __restrict__ outp, int M) {
    constexpr int G = D / 2;
    int t = blockIdx.x * blockDim.x + threadIdx.x;
    int n = t / G;
    int lane = t % G;
    if (n >= M) return;

    int cnt = g_cnt[n];
    const int2* bp = g_bpair + (size_t)n * SLOTS;

    float2 acc0, acc1;
    acc0.x = __ldg(bias + lane * 2);
    acc0.y = __ldg(bias + lane * 2 + 1);
    acc1.x = 0.f; acc1.y = 0.f;

    for (int s = 0; s < cnt; s += 4) {
        int2 p0 = __ldg(bp + s);
        int2 p1 = __ldg(bp + s + 1);
        int2 p2 = __ldg(bp + s + 2);
        int2 p3 = __ldg(bp + s + 3);
        float2 m0 = *reinterpret_cast<const float2*>(sup + (size_t)p0.x * D + lane * 2);
        float2 m1 = *reinterpret_cast<const float2*>(sup + (size_t)p1.x * D + lane * 2);
        float2 m2 = *reinterpret_cast<const float2*>(sup + (size_t)p2.x * D + lane * 2);
        float2 m3 = *reinterpret_cast<const float2*>(sup + (size_t)p3.x * D + lane * 2);
        float v0 = __int_as_float(p0.y), v1 = __int_as_float(p1.y);
        float v2 = __int_as_float(p2.y), v3 = __int_as_float(p3.y);
        acc0.x += m0.x * v0; acc0.y += m0.y * v0;
        acc1.x += m1.x * v1; acc1.y += m1.y * v1;
        acc0.x += m2.x * v2; acc0.y += m2.y * v2;
        acc1.x += m3.x * v3; acc1.y += m3.y * v3;
    }
    acc0.x += acc1.x; acc0.y += acc1.y;
    *reinterpret_cast<float2*>(outp + (size_t)n * D + lane * 2) = acc0;
}

// ---------------------------------------------------------------------------
// tf32 tensor-core GEMM:  C[M,64] = (RELU? relu(A) : A)[M,K] @ W[K,64]
// 256 threads / 8 warps. Warp w computes rows [16w,16w+16) x all 64 cols via
// 8 x m16n8k8 tf32 mma per k8-step. W staged as tf32 bits, XOR-swizzled
// (col ^ ((k&3)<<3)) for conflict-free B-fragment LDS.
// ---------------------------------------------------------------------------
template <int K, bool RELU>
__global__ void __launch_bounds__(256) mma_gemm_kernel(
    const float* __restrict__ A, const float* __restrict__ W,
    float* __restrict__ C, int M) {
    constexpr int NO = 64;
    constexpr int BM = 128, BK = 32;
    __shared__ float    Asm[BM][BK + 1];
    __shared__ unsigned Wsm[BK][NO + 1];

    const int tid = threadIdx.x;
    const int wid = tid / 32;
    const int lane = tid % 32;
    const int gid = lane / 4;      // 0..7  (row within octet)
    const int tig = lane % 4;      // 0..3  (k / col pair)
    const int row0 = blockIdx.x * BM;
    const int wr = wid * 16;

    float acc[8][4];
    #pragma unroll
    for (int j = 0; j < 8; j++)
        #pragma unroll
        for (int q = 0; q < 4; q++) acc[j][q] = 0.f;

    for (int kc = 0; kc < K; kc += BK) {
        __syncthreads();
        // Stage W chunk as tf32 bits with XOR swizzle (coalesced global read)
        #pragma unroll
        for (int i = tid; i < BK * NO; i += 256) {
            int kk = i / NO, j = i % NO;
            float w = W[(size_t)(kc + kk) * NO + j];
            unsigned t; asm("cvt.rna.tf32.f32 %0, %1;" : "=r"(t) : "f"(w));
            Wsm[kk][j ^ ((kk & 3) << 3)] = t;
        }
        // Stage A chunk (fp32, ReLU fused), coalesced
        #pragma unroll
        for (int i = 0; i < BM * BK / 256; i++) {
            int idx = i * 256 + tid;
            int r = idx / BK, kk = idx % BK;
            int gr = row0 + r;
            float a = (gr < M) ? A[(size_t)gr * K + kc + kk] : 0.f;
            if (RELU) a = fmaxf(a, 0.f);
            Asm[r][kk] = a;
        }
        __syncthreads();

        #pragma unroll
        for (int kt = 0; kt < BK / 8; kt++) {
            const int k0 = kt * 8;
            unsigned a0, a1, a2, a3;
            asm("cvt.rna.tf32.f32 %0, %1;" : "=r"(a0) : "f"(Asm[wr + gid][k0 + tig]));
            asm("cvt.rna.tf32.f32 %0, %1;" : "=r"(a1) : "f"(Asm[wr + gid + 8][k0 + tig]));
            asm("cvt.rna.tf32.f32 %0, %1;" : "=r"(a2) : "f"(Asm[wr + gid][k0 + tig + 4]));
            asm("cvt.rna.tf32.f32 %0, %1;" : "=r"(a3) : "f"(Asm[wr + gid + 8][k0 + tig + 4]));
            #pragma unroll
            for (int j = 0; j < 8; j++) {
                int c = j * 8 + gid;
                unsigned b0 = Wsm[k0 + tig][c ^ (tig << 3)];          // (k0+tig)&3 == tig
                unsigned b1 = Wsm[k0 + tig + 4][c ^ (tig << 3)];      // (k0+tig+4)&3 == tig
                asm volatile(
                    "mma.sync.aligned.m16n8k8.row.col.f32.tf32.tf32.f32 "
                    "{%0,%1,%2,%3}, {%4,%5,%6,%7}, {%8,%9}, {%0,%1,%2,%3};"
                    : "+f"(acc[j][0]), "+f"(acc[j][1]), "+f"(acc[j][2]), "+f"(acc[j][3])
                    : "r"(a0), "r"(a1), "r"(a2), "r"(a3), "r"(b0), "r"(b1));
            }
        }
    }

    // Epilogue: thread owns C[r0][2tig,2tig+1] and C[r0+8][...] per n-tile
    const int r0 = row0 + wr + gid;
    const int r1 = r0 + 8;
    #pragma unroll
    for (int j = 0; j < 8; j++) {
        int col = j * 8 + tig * 2;
        if (r0 < M)
            *reinterpret_cast<float2*>(C + (size_t)r0 * NO + col) =
                make_float2(acc[j][0], acc[j][1]);
        if (r1 < M)
            *reinterpret_cast<float2*>(C + (size_t)r1 * NO + col) =
                make_float2(acc[j][2], acc[j][3]);
    }
}

// ---------------------------------------------------------------------------
// FFMA GEMM (layer 3, NO=16): C[M,NO] = relu(A)[M,K] @ W[K,NO]
// ---------------------------------------------------------------------------
template <int K, int NO, bool RELU>
__global__ void __launch_bounds__(256) gemm_kernel(
    const float* __restrict__ A, const float* __restrict__ W,
    float* __restrict__ C, int M) {
    constexpr int BM = 128, BK = 32;
    constexpr int TX = NO / 4;
    constexpr int TY = 256 / TX;
    constexpr int TM = BM / TY;

    __shared__ float  Asm[BM][BK + 1];
    __shared__ float4 Wsm[BK][NO / 4];

    const int tid = threadIdx.x;
    const int tx = tid % TX;
    const int ty = tid / TX;
    const int row0 = blockIdx.x * BM;

    float4 acc[TM];
    #pragma unroll
    for (int i = 0; i < TM; i++) acc[i] = make_float4(0.f, 0.f, 0.f, 0.f);

    const float4* W4 = reinterpret_cast<const float4*>(W);

    for (int kc = 0; kc < K; kc += BK) {
        __syncthreads();
        #pragma unroll
        for (int i = tid; i < BK * (NO / 4); i += 256) {
            int kk = i / (NO / 4), j = i % (NO / 4);
            Wsm[kk][j] = W4[(size_t)(kc + kk) * (NO / 4) + j];
        }
        #pragma unroll
        for (int i = 0; i < BM * BK / 256; i++) {
            int idx = i * 256 + tid;
            int r = idx / BK, kk = idx % BK;
            int gr = row0 + r;
            float a = (gr < M) ? A[(size_t)gr * K + kc + kk] : 0.f;
            if (RELU) a = fmaxf(a, 0.f);
            Asm[r][kk] = a;
        }
        __syncthreads();

        #pragma unroll
        for (int kk = 0; kk < BK; kk++) {
            float4 w = Wsm[kk][tx];
            #pragma unroll
            for (int i = 0; i < TM; i++) {
                float a = Asm[ty * TM + i][kk];
                acc[i].x += a * w.x;
                acc[i].y += a * w.y;
                acc[i].z += a * w.z;
                acc[i].w += a * w.w;
            }
        }
    }

    #pragma unroll
    for (int i = 0; i < TM; i++) {
        int r = row0 + ty * TM + i;
        if (r < M)
            *reinterpret_cast<float4*>(C + (size_t)r * NO + tx * 4) = acc[i];
    }
}

// ---------------------------------------------------------------------------
// Launch
// ---------------------------------------------------------------------------
extern "C" void kernel_launch(void* const* d_in, const int* in_sizes, int n_in,
                              void* d_out, int out_size) {
    const float* x        = (const float*)d_in[0];
    const float* edge_val = (const float*)d_in[1];
    const float* W1       = (const float*)d_in[2];
    const float* b1       = (const float*)d_in[3];
    const float* W2       = (const float*)d_in[4];
    const float* b2       = (const float*)d_in[5];
    const float* W3       = (const float*)d_in[6];
    const float* b3       = (const float*)d_in[7];
    const int*   esrc     = (const int*)d_in[8];
    const int*   edst     = (const int*)d_in[9];
    float* out = (float*)d_out;

    const int N = in_sizes[0] / 128;
    const int E = in_sizes[8];

    float *sup, *hA, *hB;
    cudaGetSymbolAddress((void**)&sup, g_sup);
    cudaGetSymbolAddress((void**)&hA, g_hA);
    cudaGetSymbolAddress((void**)&hB, g_hB);

    const int gemm_blocks = (N + 127) / 128;
    const int g64_blocks  = (N * 32 + 255) / 256;   // G=32 threads/node
    const int g16_blocks  = (N * 8 + 255) / 256;    // G=8 threads/node

    // Build + pad dst-buckets once; reused by all three SpMM gathers.
    zero_cnt_kernel<<<(N + 255) / 256, 256>>>(N);
    bucket_build_kernel<<<(E + 255) / 256, 256>>>(esrc, edst, edge_val, E);
    bucket_pad_kernel<<<(N + 255) / 256, 256>>>(N);

    // Layer 1: sup = x@W1 (tf32 TC) ; hA = gather(sup) + b1
    mma_gemm_kernel<128, false><<<gemm_blocks, 256>>>(x, W1, sup, N);
    gather_spmm_kernel<64><<<g64_blocks, 256>>>(sup, b1, hA, N);

    // Layer 2: sup = relu(hA)@W2 (tf32 TC) ; hB = gather(sup) + b2
    mma_gemm_kernel<64, true><<<gemm_blocks, 256>>>(hA, W2, sup, N);
    gather_spmm_kernel<64><<<g64_blocks, 256>>>(sup, b2, hB, N);

    // Layer 3: sup = relu(hB)@W3 (FFMA, fp32) ; out = gather(sup) + b3
    gemm_kernel<64, 16, true><<<gemm_blocks, 256>>>(hB, W3, sup, N);
    gather_spmm_kernel<16><<<g16_blocks, 256>>>(sup, b3, out, N);
}

// round 11
// speedup vs baseline: 1.2050x; 1.2050x over previous
#include <cuda_runtime.h>
#include <cuda_bf16.h>

// ---------------------------------------------------------------------------
// GCN 3-layer. Per layer: support = H @ W ; agg[n] = sum_{e:dst=n} support[src_e]*val_e + b
// GEMM layers 1-2: tf32 m16n8k8 mma.sync; A and W pre-packed into FRAGMENT
//   layout in smem (tf32-converted at staging, float2 per (tig) -> 8B LDS,
//   conflict-free in 2 phases). ReLU fused into A staging.
// GEMM layer 3 (NO=16): FFMA register-tiled (full fp32).
// SpMM: gather-based, dst-bucketed packed (src,val) slots padded to x4.
// ---------------------------------------------------------------------------

#define MAX_NODES 100000
#define SLOTS 64

static __device__ float g_sup[(size_t)MAX_NODES * 64];
static __device__ float g_hA[(size_t)MAX_NODES * 64];
static __device__ float g_hB[(size_t)MAX_NODES * 64];

static __device__ int  g_cnt[MAX_NODES];
static __device__ int2 g_bpair[(size_t)MAX_NODES * SLOTS];   // (src, val bits)

// ---------------------------------------------------------------------------
// Bucket build: zero counters, slot edges by dst, pad to multiple of 4.
// ---------------------------------------------------------------------------
__global__ void zero_cnt_kernel(int n) {
    int i = blockIdx.x * blockDim.x + threadIdx.x;
    if (i < n) g_cnt[i] = 0;
}

__global__ void bucket_build_kernel(const int* __restrict__ src,
                                    const int* __restrict__ dst,
                                    const float* __restrict__ val, int E) {
    int e = blockIdx.x * blockDim.x + threadIdx.x;
    if (e >= E) return;
    int d = __ldg(dst + e);
    int slot = atomicAdd(&g_cnt[d], 1);
    if (slot < SLOTS)
        g_bpair[(size_t)d * SLOTS + slot] =
            make_int2(__ldg(src + e), __float_as_int(__ldg(val + e)));
}

__global__ void bucket_pad_kernel(int n) {
    int i = blockIdx.x * blockDim.x + threadIdx.x;
    if (i >= n) return;
    int c = min(g_cnt[i], SLOTS);
    int cp = min((c + 3) & ~3, SLOTS);
    int2* bp = g_bpair + (size_t)i * SLOTS;
    for (int s = c; s < cp; s++) bp[s] = make_int2(0, 0);
    g_cnt[i] = cp;
}

// ---------------------------------------------------------------------------
// Gather SpMM + bias:  out[n, :] = bias + sum_s sup[src_s, :] * val_s
// ---------------------------------------------------------------------------
template <int D>
__global__ void __launch_bounds__(256) gather_spmm_kernel(
    const float* __restrict__ sup, const float* __restrict__ bias,
    float* __restrict__ outp, int M) {
    constexpr int G = D / 2;
    int t = blockIdx.x * blockDim.x + threadIdx.x;
    int n = t / G;
    int lane = t % G;
    if (n >= M) return;

    int cnt = g_cnt[n];
    const int2* bp = g_bpair + (size_t)n * SLOTS;

    float2 acc0, acc1;
    acc0.x = __ldg(bias + lane * 2);
    acc0.y = __ldg(bias + lane * 2 + 1);
    acc1.x = 0.f; acc1.y = 0.f;

    for (int s = 0; s < cnt; s += 4) {
        int2 p0 = __ldg(bp + s);
        int2 p1 = __ldg(bp + s + 1);
        int2 p2 = __ldg(bp + s + 2);
        int2 p3 = __ldg(bp + s + 3);
        float2 m0 = *reinterpret_cast<const float2*>(sup + (size_t)p0.x * D + lane * 2);
        float2 m1 = *reinterpret_cast<const float2*>(sup + (size_t)p1.x * D + lane * 2);
        float2 m2 = *reinterpret_cast<const float2*>(sup + (size_t)p2.x * D + lane * 2);
        float2 m3 = *reinterpret_cast<const float2*>(sup + (size_t)p3.x * D + lane * 2);
        float v0 = __int_as_float(p0.y), v1 = __int_as_float(p1.y);
        float v2 = __int_as_float(p2.y), v3 = __int_as_float(p3.y);
        acc0.x += m0.x * v0; acc0.y += m0.y * v0;
        acc1.x += m1.x * v1; acc1.y += m1.y * v1;
        acc0.x += m2.x * v2; acc0.y += m2.y * v2;
        acc1.x += m3.x * v3; acc1.y += m3.y * v3;
    }
    acc0.x += acc1.x; acc0.y += acc1.y;
    *reinterpret_cast<float2*>(outp + (size_t)n * D + lane * 2) = acc0;
}

// ---------------------------------------------------------------------------
// tf32 tensor-core GEMM:  C[M,64] = (RELU? relu(A) : A)[M,K] @ W[K,64]
// 256 threads / 8 warps; warp w -> rows [16w,16w+16) x 64 cols.
// Smem holds FRAGMENT-PACKED tf32:
//   Af[kt][row][tig]  = (A[row][k0+tig],  A[row][k0+tig+4])   (float2)
//   Wf[kt][col][tig]  = (W[k0+tig][col],  W[k0+tig+4][col])   (float2)
// Inner loop per kt: 2 LDS.64 (A) + 8 LDS.64 (B) + 8 MMA, no cvt.
// ---------------------------------------------------------------------------
template <int K, bool RELU>
__global__ void __launch_bounds__(256) mma_gemm_kernel(
    const float* __restrict__ A, const float* __restrict__ W,
    float* __restrict__ C, int M) {
    constexpr int NO = 64;
    constexpr int BM = 128, BK = 32;
    constexpr int NKT = BK / 8;                 // 4 k8-steps per tile
    __shared__ unsigned Af[NKT][BM][4][2];      // 16 KB
    __shared__ unsigned Wf[NKT][NO][4][2];      // 8 KB

    const int tid = threadIdx.x;
    const int wid = tid / 32;
    const int lane = tid % 32;
    const int gid = lane / 4;      // 0..7
    const int tig = lane % 4;      // 0..3
    const int row0 = blockIdx.x * BM;
    const int wr = wid * 16;

    float acc[8][4];
    #pragma unroll
    for (int j = 0; j < 8; j++)
        #pragma unroll
        for (int q = 0; q < 4; q++) acc[j][q] = 0.f;

    for (int kc = 0; kc < K; kc += BK) {
        __syncthreads();
        // Stage W chunk: coalesced read, cvt to tf32, fragment-packed write
        #pragma unroll
        for (int i = tid; i < BK * NO; i += 256) {
            int kk = i / NO, j = i % NO;
            float w = W[(size_t)(kc + kk) * NO + j];
            unsigned t; asm("cvt.rna.tf32.f32 %0, %1;" : "=r"(t) : "f"(w));
            Wf[kk >> 3][j][kk & 3][(kk & 7) >> 2] = t;
        }
        // Stage A chunk: coalesced read, ReLU, cvt, fragment-packed write
        #pragma unroll
        for (int i = 0; i < BM * BK / 256; i++) {
            int idx = i * 256 + tid;
            int r = idx / BK, kk = idx % BK;
            int gr = row0 + r;
            float a = (gr < M) ? A[(size_t)gr * K + kc + kk] : 0.f;
            if (RELU) a = fmaxf(a, 0.f);
            unsigned t; asm("cvt.rna.tf32.f32 %0, %1;" : "=r"(t) : "f"(a));
            Af[kk >> 3][r][kk & 3][(kk & 7) >> 2] = t;
        }
        __syncthreads();

        #pragma unroll
        for (int kt = 0; kt < NKT; kt++) {
            // A fragment: a0=A[gid][tig], a2=A[gid][tig+4] packed; a1,a3 from +8 row
            uint2 alo = *reinterpret_cast<const uint2*>(&Af[kt][wr + gid][tig][0]);
            uint2 ahi = *reinterpret_cast<const uint2*>(&Af[kt][wr + gid + 8][tig][0]);
            #pragma unroll
            for (int j = 0; j < 8; j++) {
                uint2 b = *reinterpret_cast<const uint2*>(&Wf[kt][j * 8 + gid][tig][0]);
                asm volatile(
                    "mma.sync.aligned.m16n8k8.row.col.f32.tf32.tf32.f32 "
                    "{%0,%1,%2,%3}, {%4,%5,%6,%7}, {%8,%9}, {%0,%1,%2,%3};"
                    : "+f"(acc[j][0]), "+f"(acc[j][1]), "+f"(acc[j][2]), "+f"(acc[j][3])
                    : "r"(alo.x), "r"(ahi.x), "r"(alo.y), "r"(ahi.y),
                      "r"(b.x), "r"(b.y));
            }
        }
    }

    const int r0 = row0 + wr + gid;
    const int r1 = r0 + 8;
    #pragma unroll
    for (int j = 0; j < 8; j++) {
        int col = j * 8 + tig * 2;
        if (r0 < M)
            *reinterpret_cast<float2*>(C + (size_t)r0 * NO + col) =
                make_float2(acc[j][0], acc[j][1]);
        if (r1 < M)
            *reinterpret_cast<float2*>(C + (size_t)r1 * NO + col) =
                make_float2(acc[j][2], acc[j][3]);
    }
}

// ---------------------------------------------------------------------------
// FFMA GEMM (layer 3, NO=16): C[M,NO] = relu(A)[M,K] @ W[K,NO]
// ---------------------------------------------------------------------------
template <int K, int NO, bool RELU>
__global__ void __launch_bounds__(256) gemm_kernel(
    const float* __restrict__ A, const float* __restrict__ W,
    float* __restrict__ C, int M) {
    constexpr int BM = 128, BK = 32;
    constexpr int TX = NO / 4;
    constexpr int TY = 256 / TX;
    constexpr int TM = BM / TY;

    __shared__ float  Asm[BM][BK + 1];
    __shared__ float4 Wsm[BK][NO / 4];

    const int tid = threadIdx.x;
    const int tx = tid % TX;
    const int ty = tid / TX;
    const int row0 = blockIdx.x * BM;

    float4 acc[TM];
    #pragma unroll
    for (int i = 0; i < TM; i++) acc[i] = make_float4(0.f, 0.f, 0.f, 0.f);

    const float4* W4 = reinterpret_cast<const float4*>(W);

    for (int kc = 0; kc < K; kc += BK) {
        __syncthreads();
        #pragma unroll
        for (int i = tid; i < BK * (NO / 4); i += 256) {
            int kk = i / (NO / 4), j = i % (NO / 4);
            Wsm[kk][j] = W4[(size_t)(kc + kk) * (NO / 4) + j];
        }
        #pragma unroll
        for (int i = 0; i < BM * BK / 256; i++) {
            int idx = i * 256 + tid;
            int r = idx / BK, kk = idx % BK;
            int gr = row0 + r;
            float a = (gr < M) ? A[(size_t)gr * K + kc + kk] : 0.f;
            if (RELU) a = fmaxf(a, 0.f);
            Asm[r][kk] = a;
        }
        __syncthreads();

        #pragma unroll
        for (int kk = 0; kk < BK; kk++) {
            float4 w = Wsm[kk][tx];
            #pragma unroll
            for (int i = 0; i < TM; i++) {
                float a = Asm[ty * TM + i][kk];
                acc[i].x += a * w.x;
                acc[i].y += a * w.y;
                acc[i].z += a * w.z;
                acc[i].w += a * w.w;
            }
        }
    }

    #pragma unroll
    for (int i = 0; i < TM; i++) {
        int r = row0 + ty * TM + i;
        if (r < M)
            *reinterpret_cast<float4*>(C + (size_t)r * NO + tx * 4) = acc[i];
    }
}

// ---------------------------------------------------------------------------
// Launch
// ---------------------------------------------------------------------------
extern "C" void kernel_launch(void* const* d_in, const int* in_sizes, int n_in,
                              void* d_out, int out_size) {
    const float* x        = (const float*)d_in[0];
    const float* edge_val = (const float*)d_in[1];
    const float* W1       = (const float*)d_in[2];
    const float* b1       = (const float*)d_in[3];
    const float* W2       = (const float*)d_in[4];
    const float* b2       = (const float*)d_in[5];
    const float* W3       = (const float*)d_in[6];
    const float* b3       = (const float*)d_in[7];
    const int*   esrc     = (const int*)d_in[8];
    const int*   edst     = (const int*)d_in[9];
    float* out = (float*)d_out;

    const int N = in_sizes[0] / 128;
    const int E = in_sizes[8];

    float *sup, *hA, *hB;
    cudaGetSymbolAddress((void**)&sup, g_sup);
    cudaGetSymbolAddress((void**)&hA, g_hA);
    cudaGetSymbolAddress((void**)&hB, g_hB);

    const int gemm_blocks = (N + 127) / 128;
    const int g64_blocks  = (N * 32 + 255) / 256;
    const int g16_blocks  = (N * 8 + 255) / 256;

    zero_cnt_kernel<<<(N + 255) / 256, 256>>>(N);
    bucket_build_kernel<<<(E + 255) / 256, 256>>>(esrc, edst, edge_val, E);
    bucket_pad_kernel<<<(N + 255) / 256, 256>>>(N);

    // Layer 1: sup = x@W1 (tf32 TC) ; hA = gather(sup) + b1
    mma_gemm_kernel<128, false><<<gemm_blocks, 256>>>(x, W1, sup, N);
    gather_spmm_kernel<64><<<g64_blocks, 256>>>(sup, b1, hA, N);

    // Layer 2: sup = relu(hA)@W2 (tf32 TC) ; hB = gather(sup) + b2
    mma_gemm_kernel<64, true><<<gemm_blocks, 256>>>(hA, W2, sup, N);
    gather_spmm_kernel<64><<<g64_blocks, 256>>>(sup, b2, hB, N);

    // Layer 3: sup = relu(hB)@W3 (FFMA fp32) ; out = gather(sup) + b3
    gemm_kernel<64, 16, true><<<gemm_blocks, 256>>>(hB, W3, sup, N);
    gather_spmm_kernel<16><<<g16_blocks, 256>>>(sup, b3, out, N);
}

// round 15
// speedup vs baseline: 1.2775x; 1.0602x over previous
#include <cuda_runtime.h>
#include <cuda_bf16.h>

// ---------------------------------------------------------------------------
// GCN 3-layer. Per layer: support = H @ W ; agg[n] = sum_{e:dst=n} support[src_e]*val_e + b
// GEMM layers 1-2: tf32 m16n8k8 mma.sync; fragment-packed smem with
//   CONFLICT-FREE rotated layouts for both staging STS and MMA LDS; BK=64.
// GEMM layer 3 (NO=16): FFMA register-tiled (full fp32).
// SpMM: gather-based, dst-bucketed packed (src,val) slots padded to x4.
// ---------------------------------------------------------------------------

#define MAX_NODES 100000
#define SLOTS 64

static __device__ float g_sup[(size_t)MAX_NODES * 64];
static __device__ float g_hA[(size_t)MAX_NODES * 64];
static __device__ float g_hB[(size_t)MAX_NODES * 64];

static __device__ int  g_cnt[MAX_NODES];
static __device__ int2 g_bpair[(size_t)MAX_NODES * SLOTS];   // (src, val bits)

// ---------------------------------------------------------------------------
// Bucket build: zero counters, slot edges by dst, pad to multiple of 4.
// ---------------------------------------------------------------------------
__global__ void zero_cnt_kernel(int n) {
    int i = blockIdx.x * blockDim.x + threadIdx.x;
    if (i < n) g_cnt[i] = 0;
}

__global__ void bucket_build_kernel(const int* __restrict__ src,
                                    const int* __restrict__ dst,
                                    const float* __restrict__ val, int E) {
    int e = blockIdx.x * blockDim.x + threadIdx.x;
    if (e >= E) return;
    int d = __ldg(dst + e);
    int slot = atomicAdd(&g_cnt[d], 1);
    if (slot < SLOTS)
        g_bpair[(size_t)d * SLOTS + slot] =
            make_int2(__ldg(src + e), __float_as_int(__ldg(val + e)));
}

__global__ void bucket_pad_kernel(int n) {
    int i = blockIdx.x * blockDim.x + threadIdx.x;
    if (i >= n) return;
    int c = min(g_cnt[i], SLOTS);
    int cp = min((c + 3) & ~3, SLOTS);
    int2* bp = g_bpair + (size_t)i * SLOTS;
    for (int s = c; s < cp; s++) bp[s] = make_int2(0, 0);
    g_cnt[i] = cp;
}

// ---------------------------------------------------------------------------
// Gather SpMM + bias:  out[n, :] = bias + sum_s sup[src_s, :] * val_s
// ---------------------------------------------------------------------------
template <int D>
__global__ void __launch_bounds__(256) gather_spmm_kernel(
    const float* __restrict__ sup, const float* __restrict__ bias,
    float* __restrict__ outp, int M) {
    constexpr int G = D / 2;
    int t = blockIdx.x * blockDim.x + threadIdx.x;
    int n = t / G;
    int lane = t % G;
    if (n >= M) return;

    int cnt = g_cnt[n];
    const int2* bp = g_bpair + (size_t)n * SLOTS;

    float2 acc0, acc1;
    acc0.x = __ldg(bias + lane * 2);
    acc0.y = __ldg(bias + lane * 2 + 1);
    acc1.x = 0.f; acc1.y = 0.f;

    for (int s = 0; s < cnt; s += 4) {
        int2 p0 = __ldg(bp + s);
        int2 p1 = __ldg(bp + s + 1);
        int2 p2 = __ldg(bp + s + 2);
        int2 p3 = __ldg(bp + s + 3);
        float2 m0 = *reinterpret_cast<const float2*>(sup + (size_t)p0.x * D + lane * 2);
        float2 m1 = *reinterpret_cast<const float2*>(sup + (size_t)p1.x * D + lane * 2);
        float2 m2 = *reinterpret_cast<const float2*>(sup + (size_t)p2.x * D + lane * 2);
        float2 m3 = *reinterpret_cast<const float2*>(sup + (size_t)p3.x * D + lane * 2);
        float v0 = __int_as_float(p0.y), v1 = __int_as_float(p1.y);
        float v2 = __int_as_float(p2.y), v3 = __int_as_float(p3.y);
        acc0.x += m0.x * v0; acc0.y += m0.y * v0;
        acc1.x += m1.x * v1; acc1.y += m1.y * v1;
        acc0.x += m2.x * v2; acc0.y += m2.y * v2;
        acc1.x += m3.x * v3; acc1.y += m3.y * v3;
    }
    acc0.x += acc1.x; acc0.y += acc1.y;
    *reinterpret_cast<float2*>(outp + (size_t)n * D + lane * 2) = acc0;
}

// ---------------------------------------------------------------------------
// tf32 tensor-core GEMM:  C[M,64] = (RELU? relu(A) : A)[M,K] @ W[K,64]
// 256 threads / 8 warps; warp w -> rows [16w,16w+16) x 64 cols. BK=64.
// Conflict-free fragment-packed smem (word indices):
//   Af: r*64 + ((kt + r)&7)*8 + tig*2 + h          (32 KB, kt-plane rotated by row)
//   Wf: kt*512 + c*8 + ((tig + (c>>2))&3)*2 + h    (16 KB, tig-slot rotated by col quad)
// where (kt,tig,h) <-> kk = kt*8 + tig + 4h. Pairs (h=0,1) are uint2.
// ---------------------------------------------------------------------------
template <int K, bool RELU>
__global__ void __launch_bounds__(256) mma_gemm_kernel(
    const float* __restrict__ A, const float* __restrict__ W,
    float* __restrict__ C, int M) {
    constexpr int NO = 64;
    constexpr int BM = 128, BK = 64;
    constexpr int NKT = BK / 8;                 // 8
    __shared__ unsigned Af[BM * 64];            // 32 KB
    __shared__ unsigned Wf[NKT * 512];          // 16 KB

    const int tid = threadIdx.x;
    const int wid = tid / 32;
    const int lane = tid % 32;
    const int gid = lane / 4;      // 0..7
    const int tig = lane % 4;      // 0..3
    const int row0 = blockIdx.x * BM;
    const int wr = wid * 16;

    float acc[8][4];
    #pragma unroll
    for (int j = 0; j < 8; j++)
        #pragma unroll
        for (int q = 0; q < 4; q++) acc[j][q] = 0.f;

    for (int kc = 0; kc < K; kc += BK) {
        if (kc) __syncthreads();
        // ---- Stage W: thread owns column j = tid&63, k's (tid>>6) + 4n ----
        {
            const int j = tid & 63;
            const int ko = tid >> 6;            // 0..3, = tig of these kk's
            float wv[16];
            #pragma unroll
            for (int n = 0; n < 16; n++)
                wv[n] = W[(size_t)(kc + ko + 4 * n) * NO + j];
            const int tr = (ko + (j >> 2)) & 3;  // rotated tig slot
            #pragma unroll
            for (int m = 0; m < 8; m++) {
                unsigned lo, hi;
                asm("cvt.rna.tf32.f32 %0, %1;" : "=r"(lo) : "f"(wv[2 * m]));
                asm("cvt.rna.tf32.f32 %0, %1;" : "=r"(hi) : "f"(wv[2 * m + 1]));
                *reinterpret_cast<uint2*>(&Wf[m * 512 + j * 8 + tr * 2]) =
                    make_uint2(lo, hi);
            }
        }
        // ---- Stage A: idx -> (r = idx>>6, kk = idx&63), coalesced LDG ----
        #pragma unroll
        for (int i = 0; i < BM * BK / 256; i++) {
            int idx = i * 256 + tid;
            int r = idx >> 6, kk = idx & 63;
            int gr = row0 + r;
            float a = (gr < M) ? A[(size_t)gr * K + kc + kk] : 0.f;
            if (RELU) a = fmaxf(a, 0.f);
            unsigned t; asm("cvt.rna.tf32.f32 %0, %1;" : "=r"(t) : "f"(a));
            int kt = kk >> 3, tg = kk & 3, h = (kk >> 2) & 1;
            Af[r * 64 + (((kt + r) & 7) << 3) + tg * 2 + h] = t;
        }
        __syncthreads();

        #pragma unroll
        for (int kt = 0; kt < NKT; kt++) {
            const int ra = wr + gid, rb = ra + 8;
            uint2 alo = *reinterpret_cast<const uint2*>(
                &Af[ra * 64 + (((kt + ra) & 7) << 3) + tig * 2]);
            uint2 ahi = *reinterpret_cast<const uint2*>(
                &Af[rb * 64 + (((kt + rb) & 7) << 3) + tig * 2]);
            #pragma unroll
            for (int j = 0; j < 8; j++) {
                int c = j * 8 + gid;
                uint2 b = *reinterpret_cast<const uint2*>(
                    &Wf[kt * 512 + c * 8 + (((tig + (c >> 2)) & 3) << 1)]);
                asm volatile(
                    "mma.sync.aligned.m16n8k8.row.col.f32.tf32.tf32.f32 "
                    "{%0,%1,%2,%3}, {%4,%5,%6,%7}, {%8,%9}, {%0,%1,%2,%3};"
                    : "+f"(acc[j][0]), "+f"(acc[j][1]), "+f"(acc[j][2]), "+f"(acc[j][3])
                    : "r"(alo.x), "r"(ahi.x), "r"(alo.y), "r"(ahi.y),
                      "r"(b.x), "r"(b.y));
            }
        }
    }

    const int r0 = row0 + wr + gid;
    const int r1 = r0 + 8;
    #pragma unroll
    for (int j = 0; j < 8; j++) {
        int col = j * 8 + tig * 2;
        if (r0 < M)
            *reinterpret_cast<float2*>(C + (size_t)r0 * NO + col) =
                make_float2(acc[j][0], acc[j][1]);
        if (r1 < M)
            *reinterpret_cast<float2*>(C + (size_t)r1 * NO + col) =
                make_float2(acc[j][2], acc[j][3]);
    }
}

// ---------------------------------------------------------------------------
// FFMA GEMM (layer 3, NO=16): C[M,NO] = relu(A)[M,K] @ W[K,NO]
// ---------------------------------------------------------------------------
template <int K, int NO, bool RELU>
__global__ void __launch_bounds__(256) gemm_kernel(
    const float* __restrict__ A, const float* __restrict__ W,
    float* __restrict__ C, int M) {
    constexpr int BM = 128, BK = 32;
    constexpr int TX = NO / 4;
    constexpr int TY = 256 / TX;
    constexpr int TM = BM / TY;

    __shared__ float  Asm[BM][BK + 1];
    __shared__ float4 Wsm[BK][NO / 4];

    const int tid = threadIdx.x;
    const int tx = tid % TX;
    const int ty = tid / TX;
    const int row0 = blockIdx.x * BM;

    float4 acc[TM];
    #pragma unroll
    for (int i = 0; i < TM; i++) acc[i] = make_float4(0.f, 0.f, 0.f, 0.f);

    const float4* W4 = reinterpret_cast<const float4*>(W);

    for (int kc = 0; kc < K; kc += BK) {
        __syncthreads();
        #pragma unroll
        for (int i = tid; i < BK * (NO / 4); i += 256) {
            int kk = i / (NO / 4), j = i % (NO / 4);
            Wsm[kk][j] = W4[(size_t)(kc + kk) * (NO / 4) + j];
        }
        #pragma unroll
        for (int i = 0; i < BM * BK / 256; i++) {
            int idx = i * 256 + tid;
            int r = idx / BK, kk = idx % BK;
            int gr = row0 + r;
            float a = (gr < M) ? A[(size_t)gr * K + kc + kk] : 0.f;
            if (RELU) a = fmaxf(a, 0.f);
            Asm[r][kk] = a;
        }
        __syncthreads();

        #pragma unroll
        for (int kk = 0; kk < BK; kk++) {
            float4 w = Wsm[kk][tx];
            #pragma unroll
            for (int i = 0; i < TM; i++) {
                float a = Asm[ty * TM + i][kk];
                acc[i].x += a * w.x;
                acc[i].y += a * w.y;
                acc[i].z += a * w.z;
                acc[i].w += a * w.w;
            }
        }
    }

    #pragma unroll
    for (int i = 0; i < TM; i++) {
        int r = row0 + ty * TM + i;
        if (r < M)
            *reinterpret_cast<float4*>(C + (size_t)r * NO + tx * 4) = acc[i];
    }
}

// ---------------------------------------------------------------------------
// Launch
// ---------------------------------------------------------------------------
extern "C" void kernel_launch(void* const* d_in, const int* in_sizes, int n_in,
                              void* d_out, int out_size) {
    const float* x        = (const float*)d_in[0];
    const float* edge_val = (const float*)d_in[1];
    const float* W1       = (const float*)d_in[2];
    const float* b1       = (const float*)d_in[3];
    const float* W2       = (const float*)d_in[4];
    const float* b2       = (const float*)d_in[5];
    const float* W3       = (const float*)d_in[6];
    const float* b3       = (const float*)d_in[7];
    const int*   esrc     = (const int*)d_in[8];
    const int*   edst     = (const int*)d_in[9];
    float* out = (float*)d_out;

    const int N = in_sizes[0] / 128;
    const int E = in_sizes[8];

    float *sup, *hA, *hB;
    cudaGetSymbolAddress((void**)&sup, g_sup);
    cudaGetSymbolAddress((void**)&hA, g_hA);
    cudaGetSymbolAddress((void**)&hB, g_hB);

    const int gemm_blocks = (N + 127) / 128;
    const int g64_blocks  = (N * 32 + 255) / 256;
    const int g16_blocks  = (N * 8 + 255) / 256;

    zero_cnt_kernel<<<(N + 255) / 256, 256>>>(N);
    bucket_build_kernel<<<(E + 255) / 256, 256>>>(esrc, edst, edge_val, E);
    bucket_pad_kernel<<<(N + 255) / 256, 256>>>(N);

    // Layer 1: sup = x@W1 (tf32 TC) ; hA = gather(sup) + b1
    mma_gemm_kernel<128, false><<<gemm_blocks, 256>>>(x, W1, sup, N);
    gather_spmm_kernel<64><<<g64_blocks, 256>>>(sup, b1, hA, N);

    // Layer 2: sup = relu(hA)@W2 (tf32 TC) ; hB = gather(sup) + b2
    mma_gemm_kernel<64, true><<<gemm_blocks, 256>>>(hA, W2, sup, N);
    gather_spmm_kernel<64><<<g64_blocks, 256>>>(sup, b2, hB, N);

    // Layer 3: sup = relu(hB)@W3 (FFMA fp32) ; out = gather(sup) + b3
    gemm_kernel<64, 16, true><<<gemm_blocks, 256>>>(hB, W3, sup, N);
    gather_spmm_kernel<16><<<g16_blocks, 256>>>(sup, b3, out, N);
}

// round 17
// speedup vs baseline: 1.4800x; 1.1585x over previous
#include <cuda_runtime.h>
#include <cuda_bf16.h>
#include <cuda_fp16.h>

// ---------------------------------------------------------------------------
// GCN 3-layer. Per layer: support = H @ W ; agg[n] = sum_{e:dst=n} support[src_e]*val_e + b
// support is stored FP16 (halves the dominant gather L2 traffic); gather
// accumulates in fp32; h/agg stay fp32.
// GEMM layers 1-2: tf32 m16n8k8 mma.sync, conflict-free fragment smem, BK=64.
// GEMM layer 3 (NO=16): FFMA register-tiled.
// SpMM: gather-based, dst-bucketed packed (src,val) slots padded to x4.
// ---------------------------------------------------------------------------

#define MAX_NODES 100000
#define SLOTS 64

static __device__ __half g_sup[(size_t)MAX_NODES * 64];
static __device__ float  g_hA[(size_t)MAX_NODES * 64];
static __device__ float  g_hB[(size_t)MAX_NODES * 64];

static __device__ int  g_cnt[MAX_NODES];
static __device__ int2 g_bpair[(size_t)MAX_NODES * SLOTS];   // (src, val bits)

// ---------------------------------------------------------------------------
// Bucket build: zero counters, slot edges by dst, pad to multiple of 4.
// ---------------------------------------------------------------------------
__global__ void zero_cnt_kernel(int n) {
    int i = blockIdx.x * blockDim.x + threadIdx.x;
    if (i < n) g_cnt[i] = 0;
}

__global__ void bucket_build_kernel(const int* __restrict__ src,
                                    const int* __restrict__ dst,
                                    const float* __restrict__ val, int E) {
    int e = blockIdx.x * blockDim.x + threadIdx.x;
    if (e >= E) return;
    int d = __ldg(dst + e);
    int slot = atomicAdd(&g_cnt[d], 1);
    if (slot < SLOTS)
        g_bpair[(size_t)d * SLOTS + slot] =
            make_int2(__ldg(src + e), __float_as_int(__ldg(val + e)));
}

__global__ void bucket_pad_kernel(int n) {
    int i = blockIdx.x * blockDim.x + threadIdx.x;
    if (i >= n) return;
    int c = min(g_cnt[i], SLOTS);
    int cp = min((c + 3) & ~3, SLOTS);
    int2* bp = g_bpair + (size_t)i * SLOTS;
    for (int s = c; s < cp; s++) bp[s] = make_int2(0, 0);
    g_cnt[i] = cp;
}

// ---------------------------------------------------------------------------
// Gather SpMM + bias:  out[n, :] = bias + sum_s sup[src_s, :] * val_s
// sup is fp16 (half2 per lane); accumulate fp32; out fp32.
// ---------------------------------------------------------------------------
template <int D>
__global__ void __launch_bounds__(256) gather_spmm_kernel(
    const __half* __restrict__ sup, const float* __restrict__ bias,
    float* __restrict__ outp, int M) {
    constexpr int G = D / 2;
    int t = blockIdx.x * blockDim.x + threadIdx.x;
    int n = t / G;
    int lane = t % G;
    if (n >= M) return;

    int cnt = g_cnt[n];
    const int2* bp = g_bpair + (size_t)n * SLOTS;

    float2 acc0, acc1;
    acc0.x = __ldg(bias + lane * 2);
    acc0.y = __ldg(bias + lane * 2 + 1);
    acc1.x = 0.f; acc1.y = 0.f;

    for (int s = 0; s < cnt; s += 4) {
        int2 p0 = __ldg(bp + s);
        int2 p1 = __ldg(bp + s + 1);
        int2 p2 = __ldg(bp + s + 2);
        int2 p3 = __ldg(bp + s + 3);
        __half2 h0 = *reinterpret_cast<const __half2*>(sup + (size_t)p0.x * D + lane * 2);
        __half2 h1 = *reinterpret_cast<const __half2*>(sup + (size_t)p1.x * D + lane * 2);
        __half2 h2 = *reinterpret_cast<const __half2*>(sup + (size_t)p2.x * D + lane * 2);
        __half2 h3 = *reinterpret_cast<const __half2*>(sup + (size_t)p3.x * D + lane * 2);
        float2 m0 = __half22float2(h0);
        float2 m1 = __half22float2(h1);
        float2 m2 = __half22float2(h2);
        float2 m3 = __half22float2(h3);
        float v0 = __int_as_float(p0.y), v1 = __int_as_float(p1.y);
        float v2 = __int_as_float(p2.y), v3 = __int_as_float(p3.y);
        acc0.x += m0.x * v0; acc0.y += m0.y * v0;
        acc1.x += m1.x * v1; acc1.y += m1.y * v1;
        acc0.x += m2.x * v2; acc0.y += m2.y * v2;
        acc1.x += m3.x * v3; acc1.y += m3.y * v3;
    }
    acc0.x += acc1.x; acc0.y += acc1.y;
    *reinterpret_cast<float2*>(outp + (size_t)n * D + lane * 2) = acc0;
}

// ---------------------------------------------------------------------------
// tf32 tensor-core GEMM:  C[M,64] = (RELU? relu(A) : A)[M,K] @ W[K,64], C fp16.
// 256 threads / 8 warps; warp w -> rows [16w,16w+16) x 64 cols. BK=64.
// Conflict-free fragment-packed smem (word indices):
//   Af: r*64 + ((kt + r)&7)*8 + tig*2 + h
//   Wf: kt*512 + c*8 + ((tig + (c>>2))&3)*2 + h
// ---------------------------------------------------------------------------
template <int K, bool RELU>
__global__ void __launch_bounds__(256) mma_gemm_kernel(
    const float* __restrict__ A, const float* __restrict__ W,
    __half* __restrict__ C, int M) {
    constexpr int NO = 64;
    constexpr int BM = 128, BK = 64;
    constexpr int NKT = BK / 8;                 // 8
    __shared__ unsigned Af[BM * 64];            // 32 KB
    __shared__ unsigned Wf[NKT * 512];          // 16 KB

    const int tid = threadIdx.x;
    const int wid = tid / 32;
    const int lane = tid % 32;
    const int gid = lane / 4;      // 0..7
    const int tig = lane % 4;      // 0..3
    const int row0 = blockIdx.x * BM;
    const int wr = wid * 16;

    float acc[8][4];
    #pragma unroll
    for (int j = 0; j < 8; j++)
        #pragma unroll
        for (int q = 0; q < 4; q++) acc[j][q] = 0.f;

    for (int kc = 0; kc < K; kc += BK) {
        if (kc) __syncthreads();
        // ---- Stage W: thread owns column j = tid&63, k's (tid>>6) + 4n ----
        {
            const int j = tid & 63;
            const int ko = tid >> 6;
            float wv[16];
            #pragma unroll
            for (int n = 0; n < 16; n++)
                wv[n] = W[(size_t)(kc + ko + 4 * n) * NO + j];
            const int tr = (ko + (j >> 2)) & 3;
            #pragma unroll
            for (int m = 0; m < 8; m++) {
                unsigned lo, hi;
                asm("cvt.rna.tf32.f32 %0, %1;" : "=r"(lo) : "f"(wv[2 * m]));
                asm("cvt.rna.tf32.f32 %0, %1;" : "=r"(hi) : "f"(wv[2 * m + 1]));
                *reinterpret_cast<uint2*>(&Wf[m * 512 + j * 8 + tr * 2]) =
                    make_uint2(lo, hi);
            }
        }
        // ---- Stage A ----
        #pragma unroll
        for (int i = 0; i < BM * BK / 256; i++) {
            int idx = i * 256 + tid;
            int r = idx >> 6, kk = idx & 63;
            int gr = row0 + r;
            float a = (gr < M) ? A[(size_t)gr * K + kc + kk] : 0.f;
            if (RELU) a = fmaxf(a, 0.f);
            unsigned t; asm("cvt.rna.tf32.f32 %0, %1;" : "=r"(t) : "f"(a));
            int kt = kk >> 3, tg = kk & 3, h = (kk >> 2) & 1;
            Af[r * 64 + (((kt + r) & 7) << 3) + tg * 2 + h] = t;
        }
        __syncthreads();

        #pragma unroll
        for (int kt = 0; kt < NKT; kt++) {
            const int ra = wr + gid, rb = ra + 8;
            uint2 alo = *reinterpret_cast<const uint2*>(
                &Af[ra * 64 + (((kt + ra) & 7) << 3) + tig * 2]);
            uint2 ahi = *reinterpret_cast<const uint2*>(
                &Af[rb * 64 + (((kt + rb) & 7) << 3) + tig * 2]);
            #pragma unroll
            for (int j = 0; j < 8; j++) {
                int c = j * 8 + gid;
                uint2 b = *reinterpret_cast<const uint2*>(
                    &Wf[kt * 512 + c * 8 + (((tig + (c >> 2)) & 3) << 1)]);
                asm volatile(
                    "mma.sync.aligned.m16n8k8.row.col.f32.tf32.tf32.f32 "
                    "{%0,%1,%2,%3}, {%4,%5,%6,%7}, {%8,%9}, {%0,%1,%2,%3};"
                    : "+f"(acc[j][0]), "+f"(acc[j][1]), "+f"(acc[j][2]), "+f"(acc[j][3])
                    : "r"(alo.x), "r"(ahi.x), "r"(alo.y), "r"(ahi.y),
                      "r"(b.x), "r"(b.y));
            }
        }
    }

    const int r0 = row0 + wr + gid;
    const int r1 = r0 + 8;
    #pragma unroll
    for (int j = 0; j < 8; j++) {
        int col = j * 8 + tig * 2;
        if (r0 < M)
            *reinterpret_cast<__half2*>(C + (size_t)r0 * NO + col) =
                __floats2half2_rn(acc[j][0], acc[j][1]);
        if (r1 < M)
            *reinterpret_cast<__half2*>(C + (size_t)r1 * NO + col) =
                __floats2half2_rn(acc[j][2], acc[j][3]);
    }
}

// ---------------------------------------------------------------------------
// FFMA GEMM (layer 3, NO=16): C[M,NO] = relu(A)[M,K] @ W[K,NO], C fp16.
// ---------------------------------------------------------------------------
template <int K, int NO, bool RELU>
__global__ void __launch_bounds__(256) gemm_kernel(
    const float* __restrict__ A, const float* __restrict__ W,
    __half* __restrict__ C, int M) {
    constexpr int BM = 128, BK = 32;
    constexpr int TX = NO / 4;
    constexpr int TY = 256 / TX;
    constexpr int TM = BM / TY;

    __shared__ float  Asm[BM][BK + 1];
    __shared__ float4 Wsm[BK][NO / 4];

    const int tid = threadIdx.x;
    const int tx = tid % TX;
    const int ty = tid / TX;
    const int row0 = blockIdx.x * BM;

    float4 acc[TM];
    #pragma unroll
    for (int i = 0; i < TM; i++) acc[i] = make_float4(0.f, 0.f, 0.f, 0.f);

    const float4* W4 = reinterpret_cast<const float4*>(W);

    for (int kc = 0; kc < K; kc += BK) {
        __syncthreads();
        #pragma unroll
        for (int i = tid; i < BK * (NO / 4); i += 256) {
            int kk = i / (NO / 4), j = i % (NO / 4);
            Wsm[kk][j] = W4[(size_t)(kc + kk) * (NO / 4) + j];
        }
        #pragma unroll
        for (int i = 0; i < BM * BK / 256; i++) {
            int idx = i * 256 + tid;
            int r = idx / BK, kk = idx % BK;
            int gr = row0 + r;
            float a = (gr < M) ? A[(size_t)gr * K + kc + kk] : 0.f;
            if (RELU) a = fmaxf(a, 0.f);
            Asm[r][kk] = a;
        }
        __syncthreads();

        #pragma unroll
        for (int kk = 0; kk < BK; kk++) {
            float4 w = Wsm[kk][tx];
            #pragma unroll
            for (int i = 0; i < TM; i++) {
                float a = Asm[ty * TM + i][kk];
                acc[i].x += a * w.x;
                acc[i].y += a * w.y;
                acc[i].z += a * w.z;
                acc[i].w += a * w.w;
            }
        }
    }

    #pragma unroll
    for (int i = 0; i < TM; i++) {
        int r = row0 + ty * TM + i;
        if (r < M) {
            __half2* p = reinterpret_cast<__half2*>(C + (size_t)r * NO + tx * 4);
            p[0] = __floats2half2_rn(acc[i].x, acc[i].y);
            p[1] = __floats2half2_rn(acc[i].z, acc[i].w);
        }
    }
}

// ---------------------------------------------------------------------------
// Launch
// ---------------------------------------------------------------------------
extern "C" void kernel_launch(void* const* d_in, const int* in_sizes, int n_in,
                              void* d_out, int out_size) {
    const float* x        = (const float*)d_in[0];
    const float* edge_val = (const float*)d_in[1];
    const float* W1       = (const float*)d_in[2];
    const float* b1       = (const float*)d_in[3];
    const float* W2       = (const float*)d_in[4];
    const float* b2       = (const float*)d_in[5];
    const float* W3       = (const float*)d_in[6];
    const float* b3       = (const float*)d_in[7];
    const int*   esrc     = (const int*)d_in[8];
    const int*   edst     = (const int*)d_in[9];
    float* out = (float*)d_out;

    const int N = in_sizes[0] / 128;
    const int E = in_sizes[8];

    __half* sup;
    float *hA, *hB;
    cudaGetSymbolAddress((void**)&sup, g_sup);
    cudaGetSymbolAddress((void**)&hA, g_hA);
    cudaGetSymbolAddress((void**)&hB, g_hB);

    const int gemm_blocks = (N + 127) / 128;
    const int g64_blocks  = (N * 32 + 255) / 256;
    const int g16_blocks  = (N * 8 + 255) / 256;

    zero_cnt_kernel<<<(N + 255) / 256, 256>>>(N);
    bucket_build_kernel<<<(E + 255) / 256, 256>>>(esrc, edst, edge_val, E);
    bucket_pad_kernel<<<(N + 255) / 256, 256>>>(N);

    // Layer 1: sup = x@W1 (tf32 TC, fp16 out) ; hA = gather(sup) + b1
    mma_gemm_kernel<128, false><<<gemm_blocks, 256>>>(x, W1, sup, N);
    gather_spmm_kernel<64><<<g64_blocks, 256>>>(sup, b1, hA, N);

    // Layer 2: sup = relu(hA)@W2 (tf32 TC, fp16 out) ; hB = gather(sup) + b2
    mma_gemm_kernel<64, true><<<gemm_blocks, 256>>>(hA, W2, sup, N);
    gather_spmm_kernel<64><<<g64_blocks, 256>>>(sup, b2, hB, N);

    // Layer 3: sup = relu(hB)@W3 (FFMA, fp16 out) ; out = gather(sup) + b3
    gemm_kernel<64, 16, true><<<gemm_blocks, 256>>>(hB, W3, sup, N);
    gather_spmm_kernel<16><<<g16_blocks, 256>>>(sup, b3, out, N);
}